// round 1
// baseline (speedup 1.0000x reference)
#include <cuda_runtime.h>

#define TT 4096
#define CC 768
#define HH 12
#define DH 64

// Scratch (allocation-free rule: __device__ globals)
__device__ float g_q[HH * TT * DH];
__device__ float g_k[HH * TT * DH];
__device__ float g_v[HH * TT * DH];
__device__ float g_att[TT * CC];

// ---------------------------------------------------------------------------
// Kernel 1: fused QKV projection.
// C[t, j] for j in [0, 2304): sel = j/768 (q/k/v), h = (j%768)/64, d = j%64.
// SGEMM: BM=128, BN=64, BK=16, 256 threads, 8x4 microtile.
// ---------------------------------------------------------------------------
__global__ __launch_bounds__(256) void qkv_kernel(
    const float* __restrict__ x,
    const float* __restrict__ wq, const float* __restrict__ bq,
    const float* __restrict__ wk, const float* __restrict__ bk,
    const float* __restrict__ wv, const float* __restrict__ bv)
{
    __shared__ float As[16 * 129];   // [kk][r], padded stride 129
    __shared__ float Bs[16 * 64];    // [kk][c]

    const int tid = threadIdx.x;
    const int tr = tid >> 4;         // 0..15
    const int tc = tid & 15;         // 0..15
    const int m0 = blockIdx.x * 128;
    const int n0 = blockIdx.y * 64;  // 36 blocks -> 2304 cols

    const int sel = n0 / 768;
    const int h   = (n0 % 768) / 64;
    const float* w = (sel == 0) ? wq : (sel == 1) ? wk : wv;
    const float* b = (sel == 0) ? bq : (sel == 1) ? bk : bv;
    const float* wb = w + h * (CC * DH);

    float acc[8][4];
    #pragma unroll
    for (int i = 0; i < 8; i++)
        #pragma unroll
        for (int j = 0; j < 4; j++) acc[i][j] = 0.f;

    for (int k0 = 0; k0 < CC; k0 += 16) {
        // Load A tile: 128 rows x 16 k
        #pragma unroll
        for (int i = 0; i < 8; i++) {
            int e = tid + i * 256;
            int r = e >> 4, kk = e & 15;
            As[kk * 129 + r] = x[(m0 + r) * CC + k0 + kk];
        }
        // Load B tile: 16 k x 64 cols (d = c since n0 % 64 == 0)
        #pragma unroll
        for (int i = 0; i < 4; i++) {
            int e = tid + i * 256;
            int kk = e >> 6, c = e & 63;
            Bs[kk * 64 + c] = wb[(k0 + kk) * DH + c];
        }
        __syncthreads();
        #pragma unroll
        for (int kk = 0; kk < 16; kk++) {
            float a[8], bb[4];
            #pragma unroll
            for (int ri = 0; ri < 8; ri++) a[ri] = As[kk * 129 + tr + 16 * ri];
            #pragma unroll
            for (int ci = 0; ci < 4; ci++) bb[ci] = Bs[kk * 64 + tc + 16 * ci];
            #pragma unroll
            for (int ri = 0; ri < 8; ri++)
                #pragma unroll
                for (int ci = 0; ci < 4; ci++) acc[ri][ci] += a[ri] * bb[ci];
        }
        __syncthreads();
    }

    float* dst = (sel == 0) ? g_q : (sel == 1) ? g_k : g_v;
    #pragma unroll
    for (int ri = 0; ri < 8; ri++) {
        int r = m0 + tr + 16 * ri;
        #pragma unroll
        for (int ci = 0; ci < 4; ci++) {
            int d = tc + 16 * ci;
            dst[h * (TT * DH) + r * DH + d] = acc[ri][ci] + b[h * DH + d];
        }
    }
}

// ---------------------------------------------------------------------------
// Kernel 2: flash attention, one CTA per (query block of 64, head).
// 128 threads: tr = tid/16 (8 row groups), tc = tid%16 (16 col groups).
// S and O microtiles: 8 rows (stride 8) x 4 cols (stride 16).
// Smem: Q/K/V 64x64 fp32, XOR-swizzled (addr = r*64 + (kk ^ (r&31))),
// K buffer reused for P. Total 48 KB static.
// ---------------------------------------------------------------------------
__global__ __launch_bounds__(128) void attn_kernel()
{
    __shared__ float sQ[64 * 64];
    __shared__ float sK[64 * 64];   // reused for P
    __shared__ float sV[64 * 64];

    const int tid = threadIdx.x;
    const int tr = tid >> 4;        // 0..7
    const int tc = tid & 15;        // 0..15
    const int qb = blockIdx.x;      // 0..63
    const int h  = blockIdx.y;      // 0..11

    const float* qg = g_q + h * (TT * DH) + qb * 64 * DH;
    const float* kg = g_k + h * (TT * DH);
    const float* vg = g_v + h * (TT * DH);

    // Load Q tile (swizzled)
    for (int e = tid; e < 64 * 64; e += 128) {
        int r = e >> 6, kk = e & 63;
        sQ[r * 64 + (kk ^ (r & 31))] = qg[e];
    }

    float o[8][4];
    float m[8], l[8];
    #pragma unroll
    for (int ri = 0; ri < 8; ri++) {
        m[ri] = -1e30f; l[ri] = 0.f;
        #pragma unroll
        for (int ci = 0; ci < 4; ci++) o[ri][ci] = 0.f;
    }

    const float scale = 0.125f;  // 1/sqrt(64)

    for (int j = 0; j <= qb; j++) {
        __syncthreads();  // prev iter PV done (and Q load visible at j=0)
        // Load K, V tiles (swizzled)
        for (int e = tid; e < 64 * 64; e += 128) {
            int r = e >> 6, kk = e & 63;
            int sw = r * 64 + (kk ^ (r & 31));
            sK[sw] = kg[j * 4096 + e];
            sV[sw] = vg[j * 4096 + e];
        }
        __syncthreads();

        // S = Q K^T (64x64)
        float s[8][4];
        #pragma unroll
        for (int ri = 0; ri < 8; ri++)
            #pragma unroll
            for (int ci = 0; ci < 4; ci++) s[ri][ci] = 0.f;

        #pragma unroll 4
        for (int kk = 0; kk < 64; kk++) {
            float a[8], bb[4];
            #pragma unroll
            for (int ri = 0; ri < 8; ri++) {
                int r = tr + 8 * ri;
                a[ri] = sQ[r * 64 + (kk ^ (r & 31))];
            }
            #pragma unroll
            for (int ci = 0; ci < 4; ci++) {
                int c = tc + 16 * ci;
                bb[ci] = sK[c * 64 + (kk ^ (c & 31))];
            }
            #pragma unroll
            for (int ri = 0; ri < 8; ri++)
                #pragma unroll
                for (int ci = 0; ci < 4; ci++) s[ri][ci] += a[ri] * bb[ci];
        }

        // scale + causal mask (only the diagonal block needs masking)
        #pragma unroll
        for (int ri = 0; ri < 8; ri++)
            #pragma unroll
            for (int ci = 0; ci < 4; ci++) s[ri][ci] *= scale;
        if (j == qb) {
            #pragma unroll
            for (int ri = 0; ri < 8; ri++) {
                int r = tr + 8 * ri;
                #pragma unroll
                for (int ci = 0; ci < 4; ci++) {
                    int c = tc + 16 * ci;
                    if (c > r) s[ri][ci] = -1e30f;
                }
            }
        }

        // Online softmax: per-row max/sum across the 16 threads sharing a row
        #pragma unroll
        for (int ri = 0; ri < 8; ri++) {
            float tm = s[ri][0];
            #pragma unroll
            for (int ci = 1; ci < 4; ci++) tm = fmaxf(tm, s[ri][ci]);
            #pragma unroll
            for (int off = 8; off > 0; off >>= 1)
                tm = fmaxf(tm, __shfl_xor_sync(0xffffffffu, tm, off));
            float mn = fmaxf(m[ri], tm);
            float alpha = __expf(m[ri] - mn);
            m[ri] = mn;
            float rs = 0.f;
            #pragma unroll
            for (int ci = 0; ci < 4; ci++) {
                s[ri][ci] = __expf(s[ri][ci] - mn);
                rs += s[ri][ci];
            }
            #pragma unroll
            for (int off = 8; off > 0; off >>= 1)
                rs += __shfl_xor_sync(0xffffffffu, rs, off);
            l[ri] = l[ri] * alpha + rs;
            #pragma unroll
            for (int ci = 0; ci < 4; ci++) o[ri][ci] *= alpha;
        }

        __syncthreads();  // all threads done reading sK as K
        // Write P into sK (swizzled)
        #pragma unroll
        for (int ri = 0; ri < 8; ri++) {
            int r = tr + 8 * ri;
            #pragma unroll
            for (int ci = 0; ci < 4; ci++) {
                int c = tc + 16 * ci;
                sK[r * 64 + (c ^ (r & 31))] = s[ri][ci];
            }
        }
        __syncthreads();

        // O += P @ V
        #pragma unroll 4
        for (int c = 0; c < 64; c++) {
            float pv[8], vv[4];
            #pragma unroll
            for (int ri = 0; ri < 8; ri++) {
                int r = tr + 8 * ri;
                pv[ri] = sK[r * 64 + (c ^ (r & 31))];
            }
            #pragma unroll
            for (int ci = 0; ci < 4; ci++) {
                int d = tc + 16 * ci;
                vv[ci] = sV[c * 64 + (d ^ (c & 31))];
            }
            #pragma unroll
            for (int ri = 0; ri < 8; ri++)
                #pragma unroll
                for (int ci = 0; ci < 4; ci++) o[ri][ci] += pv[ri] * vv[ci];
        }
    }

    // Epilogue: normalize and write concat layout [t][h*64+d]
    #pragma unroll
    for (int ri = 0; ri < 8; ri++) {
        float inv = 1.f / l[ri];
        int r = qb * 64 + tr + 8 * ri;
        #pragma unroll
        for (int ci = 0; ci < 4; ci++) {
            int d = tc + 16 * ci;
            g_att[r * CC + h * DH + d] = o[ri][ci] * inv;
        }
    }
}

// ---------------------------------------------------------------------------
// Kernel 3: output projection  out = att @ wo + bo
// Same SGEMM shape as qkv_kernel. Grid (32, 12).
// ---------------------------------------------------------------------------
__global__ __launch_bounds__(256) void out_kernel(
    const float* __restrict__ wo, const float* __restrict__ bo,
    float* __restrict__ out)
{
    __shared__ float As[16 * 129];
    __shared__ float Bs[16 * 64];

    const int tid = threadIdx.x;
    const int tr = tid >> 4;
    const int tc = tid & 15;
    const int m0 = blockIdx.x * 128;
    const int n0 = blockIdx.y * 64;

    float acc[8][4];
    #pragma unroll
    for (int i = 0; i < 8; i++)
        #pragma unroll
        for (int j = 0; j < 4; j++) acc[i][j] = 0.f;

    for (int k0 = 0; k0 < CC; k0 += 16) {
        #pragma unroll
        for (int i = 0; i < 8; i++) {
            int e = tid + i * 256;
            int r = e >> 4, kk = e & 15;
            As[kk * 129 + r] = g_att[(m0 + r) * CC + k0 + kk];
        }
        #pragma unroll
        for (int i = 0; i < 4; i++) {
            int e = tid + i * 256;
            int kk = e >> 6, c = e & 63;
            Bs[kk * 64 + c] = wo[(k0 + kk) * CC + n0 + c];
        }
        __syncthreads();
        #pragma unroll
        for (int kk = 0; kk < 16; kk++) {
            float a[8], bb[4];
            #pragma unroll
            for (int ri = 0; ri < 8; ri++) a[ri] = As[kk * 129 + tr + 16 * ri];
            #pragma unroll
            for (int ci = 0; ci < 4; ci++) bb[ci] = Bs[kk * 64 + tc + 16 * ci];
            #pragma unroll
            for (int ri = 0; ri < 8; ri++)
                #pragma unroll
                for (int ci = 0; ci < 4; ci++) acc[ri][ci] += a[ri] * bb[ci];
        }
        __syncthreads();
    }

    #pragma unroll
    for (int ri = 0; ri < 8; ri++) {
        int r = m0 + tr + 16 * ri;
        #pragma unroll
        for (int ci = 0; ci < 4; ci++) {
            int c = n0 + tc + 16 * ci;
            out[r * CC + c] = acc[ri][ci] + bo[c];
        }
    }
}

extern "C" void kernel_launch(void* const* d_in, const int* in_sizes, int n_in,
                              void* d_out, int out_size)
{
    const float* x  = (const float*)d_in[0];
    const float* wq = (const float*)d_in[1];
    const float* bq = (const float*)d_in[2];
    const float* wk = (const float*)d_in[3];
    const float* bk = (const float*)d_in[4];
    const float* wv = (const float*)d_in[5];
    const float* bv = (const float*)d_in[6];
    const float* wo = (const float*)d_in[7];
    const float* bo = (const float*)d_in[8];

    qkv_kernel<<<dim3(TT / 128, (3 * CC) / 64), 256>>>(x, wq, bq, wk, bk, wv, bv);
    attn_kernel<<<dim3(TT / 64, HH), 128>>>();
    out_kernel<<<dim3(TT / 128, CC / 64), 256>>>(wo, bo, (float*)d_out);
}

// round 3
// speedup vs baseline: 5.2058x; 5.2058x over previous
#include <cuda_runtime.h>
#include <cstdint>

#define TT 4096
#define CC 768
#define HH 12
#define DH 64

// ---------------- device scratch (allocation-free rule) ----------------
__device__ float g_q  [HH * TT * DH];   // [h][t][d]
__device__ float g_k  [HH * TT * DH];   // [h][t][d]
__device__ float g_vt [HH * DH * TT];   // [h][d][t]  (V transposed)
__device__ float g_att[TT * CC];        // concat heads
__device__ float g_wt [3 * CC * CC];    // qkv weights as [j = sel*768 + h*64 + d][k]
__device__ float g_wot[CC * CC];        // wo as [n][k]

// ---------------- helpers ----------------
static __device__ __forceinline__ uint32_t tf32r(float f) {
    uint32_t u; asm("cvt.rna.tf32.f32 %0, %1;" : "=r"(u) : "f"(f)); return u;
}
static __device__ __forceinline__ float ex2(float x) {
    float y; asm("ex2.approx.f32 %0, %1;" : "=f"(y) : "f"(x)); return y;
}
// D += A(16x8) * B(8x8), tf32, row.col
static __device__ __forceinline__ void mma8(float* d, const uint32_t* a, const uint32_t* b) {
    asm volatile(
        "mma.sync.aligned.m16n8k8.row.col.f32.tf32.tf32.f32 "
        "{%0,%1,%2,%3}, {%4,%5,%6,%7}, {%8,%9}, {%0,%1,%2,%3};"
        : "+f"(d[0]), "+f"(d[1]), "+f"(d[2]), "+f"(d[3])
        : "r"(a[0]), "r"(a[1]), "r"(a[2]), "r"(a[3]), "r"(b[0]), "r"(b[1]));
}
static __device__ __forceinline__ uint4 cvt4(float4 v) {
    uint4 t; t.x = tf32r(v.x); t.y = tf32r(v.y); t.z = tf32r(v.z); t.w = tf32r(v.w);
    return t;
}

// ---------------- weight transposes ----------------
__global__ __launch_bounds__(256) void tr_head(const float* __restrict__ src, int j0) {
    __shared__ float t[64][65];
    const int k0 = blockIdx.x * 64, h = blockIdx.y;
    const float* s = src + (size_t)h * CC * DH;
    #pragma unroll
    for (int i = 0; i < 16; i++) {
        int e = threadIdx.x + i * 256; int kr = e >> 6, d = e & 63;
        t[kr][d] = s[(size_t)(k0 + kr) * DH + d];
    }
    __syncthreads();
    #pragma unroll
    for (int i = 0; i < 16; i++) {
        int e = threadIdx.x + i * 256; int d = e >> 6, kr = e & 63;
        g_wt[(size_t)(j0 + h * DH + d) * CC + k0 + kr] = t[kr][d];
    }
}
__global__ __launch_bounds__(256) void tr_wo(const float* __restrict__ wo) {
    __shared__ float t[64][65];
    const int c0 = blockIdx.x * 64, n0 = blockIdx.y * 64;
    #pragma unroll
    for (int i = 0; i < 16; i++) {
        int e = threadIdx.x + i * 256; int cr = e >> 6, n = e & 63;
        t[cr][n] = wo[(size_t)(c0 + cr) * CC + n0 + n];
    }
    __syncthreads();
    #pragma unroll
    for (int i = 0; i < 16; i++) {
        int e = threadIdx.x + i * 256; int n = e >> 6, cr = e & 63;
        g_wot[(size_t)(n0 + n) * CC + c0 + cr] = t[cr][n];
    }
}

// ---------------- GEMM (tf32 mma.sync): MODE 0 = qkv, MODE 1 = out ----------------
// C tile 128 x 128, BK = 32, 8 warps (4 m x 2 n), warp tile 32 x 64.
// smem per buffer: A[128][36] + B[128][36] tf32 bits. Double-buffered.
#define GBUF 4608              // 128*36 u32 per matrix
#define GBUFSZ 9216            // per buffer (A+B)

template <int MODE>
__global__ __launch_bounds__(256, 2) void gemm_k(
    const float* __restrict__ Am, const float* __restrict__ Bm,
    const float* __restrict__ x0, const float* __restrict__ x1,
    const float* __restrict__ x2, float* __restrict__ outp)
{
    extern __shared__ uint32_t sm[];
    const int tid = threadIdx.x;
    const int warp = tid >> 5, lane = tid & 31;
    const int g = lane >> 2, q = lane & 3;
    const int warp_m = warp & 3, warp_n = warp >> 2;
    const int m0 = blockIdx.x * 128, n0 = blockIdx.y * 128;

    float4 ra[4], rb[4];
    auto ldg = [&](int k0) {
        #pragma unroll
        for (int i = 0; i < 4; i++) {
            int idx = tid + i * 256; int r = idx >> 3, cc = idx & 7;
            ra[i] = *(const float4*)(Am + (size_t)(m0 + r) * CC + k0 + cc * 4);
            rb[i] = *(const float4*)(Bm + (size_t)(n0 + r) * CC + k0 + cc * 4);
        }
    };
    auto sts = [&](int buf) {
        uint32_t* sA = sm + buf * GBUFSZ;
        uint32_t* sB = sA + GBUF;
        #pragma unroll
        for (int i = 0; i < 4; i++) {
            int idx = tid + i * 256; int r = idx >> 3, cc = idx & 7;
            *(uint4*)(sA + r * 36 + cc * 4) = cvt4(ra[i]);
            *(uint4*)(sB + r * 36 + cc * 4) = cvt4(rb[i]);
        }
    };

    float Cf[2][8][4];
    #pragma unroll
    for (int tm = 0; tm < 2; tm++)
        #pragma unroll
        for (int tn = 0; tn < 8; tn++)
            #pragma unroll
            for (int k = 0; k < 4; k++) Cf[tm][tn][k] = 0.f;

    ldg(0);
    sts(0);
    __syncthreads();

    for (int c = 0; c < 24; c++) {
        if (c < 23) ldg((c + 1) * 32);
        const uint32_t* sA = sm + (c & 1) * GBUFSZ;
        const uint32_t* sB = sA + GBUF;
        #pragma unroll
        for (int ks = 0; ks < 4; ks++) {
            uint32_t a[2][4];
            #pragma unroll
            for (int tm = 0; tm < 2; tm++) {
                int row = warp_m * 32 + tm * 16 + g;
                a[tm][0] = sA[row * 36 + ks * 8 + q];
                a[tm][1] = sA[(row + 8) * 36 + ks * 8 + q];
                a[tm][2] = sA[row * 36 + ks * 8 + q + 4];
                a[tm][3] = sA[(row + 8) * 36 + ks * 8 + q + 4];
            }
            #pragma unroll
            for (int tn = 0; tn < 8; tn++) {
                uint32_t b[2];
                int col = warp_n * 64 + tn * 8 + g;
                b[0] = sB[col * 36 + ks * 8 + q];
                b[1] = sB[col * 36 + ks * 8 + q + 4];
                mma8(Cf[0][tn], a[0], b);
                mma8(Cf[1][tn], a[1], b);
            }
        }
        if (c < 23) sts((c + 1) & 1);
        __syncthreads();
    }

    const int jb = n0 + warp_n * 64;   // 64-aligned output column base
    if (MODE == 0) {
        const int sel = jb / CC, rem = jb % CC, h = rem >> 6;
        const float* bias = (sel == 0) ? x0 : (sel == 1) ? x1 : x2;
        #pragma unroll
        for (int tm = 0; tm < 2; tm++) {
            const int t0 = m0 + warp_m * 32 + tm * 16 + g;
            #pragma unroll
            for (int tn = 0; tn < 8; tn++) {
                const int d = tn * 8 + 2 * q;
                const float b0 = bias[h * DH + d], b1 = bias[h * DH + d + 1];
                if (sel < 2) {
                    float* dst = ((sel == 0) ? g_q : g_k) + (size_t)h * TT * DH;
                    float2 v0 = { Cf[tm][tn][0] + b0, Cf[tm][tn][1] + b1 };
                    float2 v1 = { Cf[tm][tn][2] + b0, Cf[tm][tn][3] + b1 };
                    *(float2*)(dst + (size_t)t0 * DH + d) = v0;
                    *(float2*)(dst + (size_t)(t0 + 8) * DH + d) = v1;
                } else {
                    float* dst = g_vt + (size_t)h * DH * TT;
                    dst[(size_t)d * TT + t0]           = Cf[tm][tn][0] + b0;
                    dst[(size_t)(d + 1) * TT + t0]     = Cf[tm][tn][1] + b1;
                    dst[(size_t)d * TT + t0 + 8]       = Cf[tm][tn][2] + b0;
                    dst[(size_t)(d + 1) * TT + t0 + 8] = Cf[tm][tn][3] + b1;
                }
            }
        }
    } else {
        const float* bo = x0;
        #pragma unroll
        for (int tm = 0; tm < 2; tm++) {
            const int t0 = m0 + warp_m * 32 + tm * 16 + g;
            #pragma unroll
            for (int tn = 0; tn < 8; tn++) {
                const int j = jb + tn * 8 + 2 * q;
                const float b0 = bo[j], b1 = bo[j + 1];
                float2 v0 = { Cf[tm][tn][0] + b0, Cf[tm][tn][1] + b1 };
                float2 v1 = { Cf[tm][tn][2] + b0, Cf[tm][tn][3] + b1 };
                *(float2*)(outp + (size_t)t0 * CC + j) = v0;
                *(float2*)(outp + (size_t)(t0 + 8) * CC + j) = v1;
            }
        }
    }
}

// ---------------- flash attention (tf32 mma.sync) ----------------
// 256 threads = 8 warps; Q block 128 rows (warp = 16 rows); key blocks of 64.
// smem (u32, tf32 bits): Qs[128][68] @0, Ks[64][68] @8704, Vs(d-major)[64][68] @13056,
//                        Ps[128][68] @17408. Total 26112 u32 = 104448 B.
__global__ __launch_bounds__(256, 2) void attn()
{
    extern __shared__ uint32_t sm[];
    uint32_t* Qs = sm;
    uint32_t* Ks = sm + 8704;
    uint32_t* Vs = sm + 13056;
    uint32_t* Ps = sm + 17408;

    const int tid = threadIdx.x;
    const int warp = tid >> 5, lane = tid & 31;
    const int g = lane >> 2, q = lane & 3;
    const int qb = 31 - blockIdx.x;    // largest work first
    const int h  = blockIdx.y;

    const float* Qg = g_q  + (size_t)h * TT * DH + (size_t)qb * 128 * DH;
    const float* Kg = g_k  + (size_t)h * TT * DH;
    const float* Vg = g_vt + (size_t)h * DH * TT;

    const float c1 = 0.18033688011112042f;   // 0.125 * log2(e)

    // Q tile: scale by c1, convert, store
    #pragma unroll
    for (int i = 0; i < 8; i++) {
        int idx = tid + i * 256; int r = idx >> 4, cc = idx & 15;
        float4 v = *(const float4*)(Qg + (size_t)r * DH + cc * 4);
        v.x *= c1; v.y *= c1; v.z *= c1; v.w *= c1;
        *(uint4*)(Qs + r * 68 + cc * 4) = cvt4(v);
    }

    float O[8][4];
    #pragma unroll
    for (int tn = 0; tn < 8; tn++)
        #pragma unroll
        for (int k = 0; k < 4; k++) O[tn][k] = 0.f;
    float m0v = -1e30f, m1v = -1e30f, l0 = 0.f, l1 = 0.f;

    const int mrow = warp * 16 + g;          // local row (and +8)
    const int r0 = qb * 128 + mrow;
    const int r1 = r0 + 8;
    const int nj = 2 * qb + 2;

    for (int j = 0; j < nj; j++) {
        __syncthreads();
        // K [64 keys][64 d], V (d-major) [64 d][64 keys]
        #pragma unroll
        for (int i = 0; i < 4; i++) {
            int idx = tid + i * 256; int r = idx >> 4, cc = idx & 15;
            float4 kv = *(const float4*)(Kg + (size_t)(j * 64 + r) * DH + cc * 4);
            *(uint4*)(Ks + r * 68 + cc * 4) = cvt4(kv);
            float4 vv = *(const float4*)(Vg + (size_t)r * TT + j * 64 + cc * 4);
            *(uint4*)(Vs + r * 68 + cc * 4) = cvt4(vv);
        }
        __syncthreads();

        // S = Qs @ Ks^T  (rows = queries, cols = keys), already in log2 domain
        float S[8][4];
        #pragma unroll
        for (int tn = 0; tn < 8; tn++)
            #pragma unroll
            for (int k = 0; k < 4; k++) S[tn][k] = 0.f;
        #pragma unroll
        for (int ks = 0; ks < 8; ks++) {
            uint32_t a[4];
            a[0] = Qs[mrow * 68 + ks * 8 + q];
            a[1] = Qs[(mrow + 8) * 68 + ks * 8 + q];
            a[2] = Qs[mrow * 68 + ks * 8 + q + 4];
            a[3] = Qs[(mrow + 8) * 68 + ks * 8 + q + 4];
            #pragma unroll
            for (int tn = 0; tn < 8; tn++) {
                uint32_t b[2];
                b[0] = Ks[(tn * 8 + g) * 68 + ks * 8 + q];
                b[1] = Ks[(tn * 8 + g) * 68 + ks * 8 + q + 4];
                mma8(S[tn], a, b);
            }
        }

        // causal mask (only the two diagonal key-blocks can clip)
        if (j >= 2 * qb) {
            const int kb = j * 64;
            #pragma unroll
            for (int tn = 0; tn < 8; tn++) {
                const int col = kb + tn * 8 + 2 * q;
                if (col > r0)     S[tn][0] = -1e30f;
                if (col + 1 > r0) S[tn][1] = -1e30f;
                if (col > r1)     S[tn][2] = -1e30f;
                if (col + 1 > r1) S[tn][3] = -1e30f;
            }
        }

        // online softmax (rows r0, r1); quad = lanes sharing a row
        float tm0 = -1e30f, tm1 = -1e30f;
        #pragma unroll
        for (int tn = 0; tn < 8; tn++) {
            tm0 = fmaxf(tm0, fmaxf(S[tn][0], S[tn][1]));
            tm1 = fmaxf(tm1, fmaxf(S[tn][2], S[tn][3]));
        }
        tm0 = fmaxf(tm0, __shfl_xor_sync(0xffffffffu, tm0, 1));
        tm0 = fmaxf(tm0, __shfl_xor_sync(0xffffffffu, tm0, 2));
        tm1 = fmaxf(tm1, __shfl_xor_sync(0xffffffffu, tm1, 1));
        tm1 = fmaxf(tm1, __shfl_xor_sync(0xffffffffu, tm1, 2));
        const float mn0 = fmaxf(m0v, tm0), mn1 = fmaxf(m1v, tm1);
        const float al0 = ex2(m0v - mn0), al1 = ex2(m1v - mn1);
        m0v = mn0; m1v = mn1;

        float rs0 = 0.f, rs1 = 0.f;
        #pragma unroll
        for (int tn = 0; tn < 8; tn++) {
            S[tn][0] = ex2(S[tn][0] - mn0);
            S[tn][1] = ex2(S[tn][1] - mn0);
            S[tn][2] = ex2(S[tn][2] - mn1);
            S[tn][3] = ex2(S[tn][3] - mn1);
            rs0 += S[tn][0] + S[tn][1];
            rs1 += S[tn][2] + S[tn][3];
        }
        rs0 += __shfl_xor_sync(0xffffffffu, rs0, 1);
        rs0 += __shfl_xor_sync(0xffffffffu, rs0, 2);
        rs1 += __shfl_xor_sync(0xffffffffu, rs1, 1);
        rs1 += __shfl_xor_sync(0xffffffffu, rs1, 2);
        l0 = l0 * al0 + rs0;
        l1 = l1 * al1 + rs1;

        // P -> smem (warp-private rows; C-layout -> A-layout via smem)
        #pragma unroll
        for (int tn = 0; tn < 8; tn++) {
            uint2 p0 = { tf32r(S[tn][0]), tf32r(S[tn][1]) };
            uint2 p1 = { tf32r(S[tn][2]), tf32r(S[tn][3]) };
            *(uint2*)(Ps + mrow * 68 + tn * 8 + 2 * q) = p0;
            *(uint2*)(Ps + (mrow + 8) * 68 + tn * 8 + 2 * q) = p1;
        }
        __syncwarp();

        // rescale O and accumulate P @ V (cols = d)
        #pragma unroll
        for (int tn = 0; tn < 8; tn++) {
            O[tn][0] *= al0; O[tn][1] *= al0;
            O[tn][2] *= al1; O[tn][3] *= al1;
        }
        #pragma unroll
        for (int ks = 0; ks < 8; ks++) {
            uint32_t a[4];
            a[0] = Ps[mrow * 68 + ks * 8 + q];
            a[1] = Ps[(mrow + 8) * 68 + ks * 8 + q];
            a[2] = Ps[mrow * 68 + ks * 8 + q + 4];
            a[3] = Ps[(mrow + 8) * 68 + ks * 8 + q + 4];
            #pragma unroll
            for (int tn = 0; tn < 8; tn++) {
                uint32_t b[2];
                b[0] = Vs[(tn * 8 + g) * 68 + ks * 8 + q];
                b[1] = Vs[(tn * 8 + g) * 68 + ks * 8 + q + 4];
                mma8(O[tn], a, b);
            }
        }
    }

    // epilogue
    const float i0 = 1.f / l0, i1 = 1.f / l1;
    #pragma unroll
    for (int tn = 0; tn < 8; tn++) {
        const int d = tn * 8 + 2 * q;
        float2 v0 = { O[tn][0] * i0, O[tn][1] * i0 };
        float2 v1 = { O[tn][2] * i1, O[tn][3] * i1 };
        *(float2*)(g_att + (size_t)r0 * CC + h * DH + d) = v0;
        *(float2*)(g_att + (size_t)r1 * CC + h * DH + d) = v1;
    }
}

// ---------------- launcher ----------------
extern "C" void kernel_launch(void* const* d_in, const int* in_sizes, int n_in,
                              void* d_out, int out_size)
{
    const float* x  = (const float*)d_in[0];
    const float* wq = (const float*)d_in[1];
    const float* bq = (const float*)d_in[2];
    const float* wk = (const float*)d_in[3];
    const float* bk = (const float*)d_in[4];
    const float* wv = (const float*)d_in[5];
    const float* bv = (const float*)d_in[6];
    const float* wo = (const float*)d_in[7];
    const float* bo = (const float*)d_in[8];

    static float* g_wt_p = nullptr;    // resolved device pointers not needed; kernels use globals

    const int GSM = 2 * GBUFSZ * 4;    // 73728 B
    const int ASM = 26112 * 4;         // 104448 B
    cudaFuncSetAttribute(gemm_k<0>, cudaFuncAttributeMaxDynamicSharedMemorySize, GSM);
    cudaFuncSetAttribute(gemm_k<1>, cudaFuncAttributeMaxDynamicSharedMemorySize, GSM);
    cudaFuncSetAttribute(attn,      cudaFuncAttributeMaxDynamicSharedMemorySize, ASM);
    (void)g_wt_p;

    tr_head<<<dim3(12, 12), 256>>>(wq, 0);
    tr_head<<<dim3(12, 12), 256>>>(wk, CC);
    tr_head<<<dim3(12, 12), 256>>>(wv, 2 * CC);
    tr_wo  <<<dim3(12, 12), 256>>>(wo);

    // qkv: A = x, B = g_wt (device global; pass via helper pointer trick)
    float* wt_dev;  cudaGetSymbolAddress((void**)&wt_dev,  g_wt);
    float* wot_dev; cudaGetSymbolAddress((void**)&wot_dev, g_wot);
    float* att_dev; cudaGetSymbolAddress((void**)&att_dev, g_att);

    gemm_k<0><<<dim3(32, 18), 256, GSM>>>(x, wt_dev, bq, bk, bv, nullptr);
    attn<<<dim3(32, 12), 256, ASM>>>();
    gemm_k<1><<<dim3(32, 6), 256, GSM>>>(att_dev, wot_dev, bo, nullptr, nullptr, (float*)d_out);
}

// round 4
// speedup vs baseline: 5.3687x; 1.0313x over previous
#include <cuda_runtime.h>
#include <cstdint>

#define TT 4096
#define CC 768
#define HH 12
#define DH 64

// ---------------- device scratch (allocation-free rule) ----------------
// All of these hold tf32 bit patterns (stored as float) except where noted.
__device__ float g_xt [TT * CC];        // x, tf32-rounded
__device__ float g_q  [HH * TT * DH];   // [h][t][d], pre-scaled by 0.125*log2e, tf32
__device__ float g_k  [HH * TT * DH];   // [h][t][d], tf32
__device__ float g_vt [HH * DH * TT];   // [h][d][t], tf32
__device__ float g_att[TT * CC];        // concat heads, tf32
__device__ float g_wt [3 * CC * CC];    // qkv weights [j = sel*768 + h*64 + d][k], tf32
__device__ float g_wot[CC * CC];        // wo as [n][k], tf32

// ---------------- helpers ----------------
static __device__ __forceinline__ uint32_t smem_u32(const void* p) {
    uint32_t a;
    asm("{ .reg .u64 t; cvta.to.shared.u64 t, %1; cvt.u32.u64 %0, t; }" : "=r"(a) : "l"(p));
    return a;
}
static __device__ __forceinline__ uint32_t tf32r(float f) {
    uint32_t u; asm("cvt.rna.tf32.f32 %0, %1;" : "=r"(u) : "f"(f)); return u;
}
static __device__ __forceinline__ float ex2(float x) {
    float y; asm("ex2.approx.f32 %0, %1;" : "=f"(y) : "f"(x)); return y;
}
static __device__ __forceinline__ void mma8(float* d, const uint32_t* a, const uint32_t* b) {
    asm volatile(
        "mma.sync.aligned.m16n8k8.row.col.f32.tf32.tf32.f32 "
        "{%0,%1,%2,%3}, {%4,%5,%6,%7}, {%8,%9}, {%0,%1,%2,%3};"
        : "+f"(d[0]), "+f"(d[1]), "+f"(d[2]), "+f"(d[3])
        : "r"(a[0]), "r"(a[1]), "r"(a[2]), "r"(a[3]), "r"(b[0]), "r"(b[1]));
}
static __device__ __forceinline__ uint4 cvt4(float4 v) {
    uint4 t; t.x = tf32r(v.x); t.y = tf32r(v.y); t.z = tf32r(v.z); t.w = tf32r(v.w);
    return t;
}
static __device__ __forceinline__ void cpa(uint32_t dst, const void* src) {
    asm volatile("cp.async.cg.shared.global [%0], [%1], 16;" :: "r"(dst), "l"(src));
}
static __device__ __forceinline__ void cp_commit() {
    asm volatile("cp.async.commit_group;" ::: "memory");
}
template <int N> static __device__ __forceinline__ void cp_wait() {
    asm volatile("cp.async.wait_group %0;" :: "n"(N) : "memory");
}

// ---------------- producers: tf32 pre-conversion ----------------
__global__ __launch_bounds__(256) void cvt_x(const float* __restrict__ x) {
    int i = blockIdx.x * 256 + threadIdx.x;
    float4 v = ((const float4*)x)[i];
    ((uint4*)g_xt)[i] = cvt4(v);
}
__global__ __launch_bounds__(256) void tr_head(const float* __restrict__ src, int j0) {
    __shared__ float t[64][65];
    const int k0 = blockIdx.x * 64, h = blockIdx.y;
    const float* s = src + (size_t)h * CC * DH;
    #pragma unroll
    for (int i = 0; i < 16; i++) {
        int e = threadIdx.x + i * 256; int kr = e >> 6, d = e & 63;
        t[kr][d] = s[(size_t)(k0 + kr) * DH + d];
    }
    __syncthreads();
    #pragma unroll
    for (int i = 0; i < 16; i++) {
        int e = threadIdx.x + i * 256; int d = e >> 6, kr = e & 63;
        g_wt[(size_t)(j0 + h * DH + d) * CC + k0 + kr] = __uint_as_float(tf32r(t[kr][d]));
    }
}
__global__ __launch_bounds__(256) void tr_wo(const float* __restrict__ wo) {
    __shared__ float t[64][65];
    const int c0 = blockIdx.x * 64, n0 = blockIdx.y * 64;
    #pragma unroll
    for (int i = 0; i < 16; i++) {
        int e = threadIdx.x + i * 256; int cr = e >> 6, n = e & 63;
        t[cr][n] = wo[(size_t)(c0 + cr) * CC + n0 + n];
    }
    __syncthreads();
    #pragma unroll
    for (int i = 0; i < 16; i++) {
        int e = threadIdx.x + i * 256; int n = e >> 6, cr = e & 63;
        g_wot[(size_t)(n0 + n) * CC + c0 + cr] = __uint_as_float(tf32r(t[cr][n]));
    }
}

// ---------------- GEMM (tf32 mma.sync + cp.async): MODE 0 = qkv, MODE 1 = out --------
// C tile 128 x 128, BK = 32, 8 warps (4 m x 2 n), warp tile 32 x 64. Double-buffered.
#define GBUF 4608              // 128*36 u32 per matrix
#define GBUFSZ 9216            // per buffer (A+B)

template <int MODE>
__global__ __launch_bounds__(256, 2) void gemm_k(
    const float* __restrict__ Am, const float* __restrict__ Bm,
    const float* __restrict__ x0, const float* __restrict__ x1,
    const float* __restrict__ x2, float* __restrict__ outp)
{
    extern __shared__ uint32_t sm[];
    const uint32_t usm = smem_u32(sm);
    const int tid = threadIdx.x;
    const int warp = tid >> 5, lane = tid & 31;
    const int g = lane >> 2, q = lane & 3;
    const int warp_m = warp & 3, warp_n = warp >> 2;
    const int m0 = blockIdx.x * 128, n0 = blockIdx.y * 128;

    auto ldgsts = [&](int k0, int buf) {
        const uint32_t uA = usm + buf * GBUFSZ * 4;
        const uint32_t uB = uA + GBUF * 4;
        #pragma unroll
        for (int i = 0; i < 4; i++) {
            int idx = tid + i * 256; int r = idx >> 3, cc = idx & 7;
            cpa(uA + (r * 36 + cc * 4) * 4, Am + (size_t)(m0 + r) * CC + k0 + cc * 4);
            cpa(uB + (r * 36 + cc * 4) * 4, Bm + (size_t)(n0 + r) * CC + k0 + cc * 4);
        }
        cp_commit();
    };

    float Cf[2][8][4];
    #pragma unroll
    for (int tm = 0; tm < 2; tm++)
        #pragma unroll
        for (int tn = 0; tn < 8; tn++)
            #pragma unroll
            for (int k = 0; k < 4; k++) Cf[tm][tn][k] = 0.f;

    ldgsts(0, 0);

    for (int c = 0; c < 24; c++) {
        cp_wait<0>();
        __syncthreads();
        if (c < 23) ldgsts((c + 1) * 32, (c + 1) & 1);
        const uint32_t* sA = sm + (c & 1) * GBUFSZ;
        const uint32_t* sB = sA + GBUF;
        #pragma unroll
        for (int ks = 0; ks < 4; ks++) {
            uint32_t a[2][4];
            #pragma unroll
            for (int tm = 0; tm < 2; tm++) {
                int row = warp_m * 32 + tm * 16 + g;
                a[tm][0] = sA[row * 36 + ks * 8 + q];
                a[tm][1] = sA[(row + 8) * 36 + ks * 8 + q];
                a[tm][2] = sA[row * 36 + ks * 8 + q + 4];
                a[tm][3] = sA[(row + 8) * 36 + ks * 8 + q + 4];
            }
            #pragma unroll
            for (int tn = 0; tn < 8; tn++) {
                uint32_t b[2];
                int col = warp_n * 64 + tn * 8 + g;
                b[0] = sB[col * 36 + ks * 8 + q];
                b[1] = sB[col * 36 + ks * 8 + q + 4];
                mma8(Cf[0][tn], a[0], b);
                mma8(Cf[1][tn], a[1], b);
            }
        }
        __syncthreads();
    }

    const int jb = n0 + warp_n * 64;   // 64-aligned output column base
    if (MODE == 0) {
        const float c1 = 0.18033688011112042f;   // 0.125 * log2(e)
        const int sel = jb / CC, rem = jb % CC, h = rem >> 6;
        const float* bias = (sel == 0) ? x0 : (sel == 1) ? x1 : x2;
        #pragma unroll
        for (int tm = 0; tm < 2; tm++) {
            const int t0 = m0 + warp_m * 32 + tm * 16 + g;
            #pragma unroll
            for (int tn = 0; tn < 8; tn++) {
                const int d = tn * 8 + 2 * q;
                const float b0 = bias[h * DH + d], b1 = bias[h * DH + d + 1];
                float v00 = Cf[tm][tn][0] + b0, v01 = Cf[tm][tn][1] + b1;
                float v10 = Cf[tm][tn][2] + b0, v11 = Cf[tm][tn][3] + b1;
                if (sel == 0) {
                    float* dst = g_q + (size_t)h * TT * DH;
                    uint2 p0 = { tf32r(v00 * c1), tf32r(v01 * c1) };
                    uint2 p1 = { tf32r(v10 * c1), tf32r(v11 * c1) };
                    *(uint2*)(dst + (size_t)t0 * DH + d) = p0;
                    *(uint2*)(dst + (size_t)(t0 + 8) * DH + d) = p1;
                } else if (sel == 1) {
                    float* dst = g_k + (size_t)h * TT * DH;
                    uint2 p0 = { tf32r(v00), tf32r(v01) };
                    uint2 p1 = { tf32r(v10), tf32r(v11) };
                    *(uint2*)(dst + (size_t)t0 * DH + d) = p0;
                    *(uint2*)(dst + (size_t)(t0 + 8) * DH + d) = p1;
                } else {
                    float* dst = g_vt + (size_t)h * DH * TT;
                    dst[(size_t)d * TT + t0]           = __uint_as_float(tf32r(v00));
                    dst[(size_t)(d + 1) * TT + t0]     = __uint_as_float(tf32r(v01));
                    dst[(size_t)d * TT + t0 + 8]       = __uint_as_float(tf32r(v10));
                    dst[(size_t)(d + 1) * TT + t0 + 8] = __uint_as_float(tf32r(v11));
                }
            }
        }
    } else {
        const float* bo = x0;
        #pragma unroll
        for (int tm = 0; tm < 2; tm++) {
            const int t0 = m0 + warp_m * 32 + tm * 16 + g;
            #pragma unroll
            for (int tn = 0; tn < 8; tn++) {
                const int j = jb + tn * 8 + 2 * q;
                const float b0 = bo[j], b1 = bo[j + 1];
                float2 v0 = { Cf[tm][tn][0] + b0, Cf[tm][tn][1] + b1 };
                float2 v1 = { Cf[tm][tn][2] + b0, Cf[tm][tn][3] + b1 };
                *(float2*)(outp + (size_t)t0 * CC + j) = v0;
                *(float2*)(outp + (size_t)(t0 + 8) * CC + j) = v1;
            }
        }
    }
}

// ---------------- flash attention (tf32 mma.sync + cp.async) ----------------
// 256 threads = 8 warps; Q block 128 rows (warp = 16 rows); key blocks of 64.
// smem (u32): Ps[128][68] @0 (Q staging then P), K[2][64][68] @8704, V[2][64][68] @17408.
// Total 26112 u32 = 104448 B. Q fragments live in registers for the whole loop.
#define ABUF 4352   // 64*68

__global__ __launch_bounds__(256, 2) void attn()
{
    extern __shared__ uint32_t sm[];
    uint32_t* Ps = sm;
    const uint32_t uPs = smem_u32(sm);

    const int tid = threadIdx.x;
    const int warp = tid >> 5, lane = tid & 31;
    const int g = lane >> 2, q = lane & 3;
    const int qb = 31 - blockIdx.x;    // largest work first
    const int h  = blockIdx.y;

    const float* Qg = g_q  + (size_t)h * TT * DH + (size_t)qb * 128 * DH;
    const float* Kg = g_k  + (size_t)h * TT * DH;
    const float* Vg = g_vt + (size_t)h * DH * TT;

    const int mrow = warp * 16 + g;
    const int r0 = qb * 128 + mrow;
    const int r1 = r0 + 8;
    const int nj = 2 * qb + 2;

    auto load_kv = [&](int j, int buf) {
        const uint32_t uK = uPs + (8704 + buf * ABUF) * 4;
        const uint32_t uV = uPs + (17408 + buf * ABUF) * 4;
        #pragma unroll
        for (int i = 0; i < 4; i++) {
            int idx = tid + i * 256; int r = idx >> 4, cc = idx & 15;
            cpa(uK + (r * 68 + cc * 4) * 4, Kg + (size_t)(j * 64 + r) * DH + cc * 4);
            cpa(uV + (r * 68 + cc * 4) * 4, Vg + (size_t)r * TT + j * 64 + cc * 4);
        }
        cp_commit();
    };

    // stage Q into Ps and prefetch KV block 0
    #pragma unroll
    for (int i = 0; i < 8; i++) {
        int idx = tid + i * 256; int r = idx >> 4, cc = idx & 15;
        cpa(uPs + (r * 68 + cc * 4) * 4, Qg + (size_t)r * DH + cc * 4);
    }
    cp_commit();
    load_kv(0, 0);
    cp_wait<0>();
    __syncthreads();

    // Q fragments -> registers (held for all iterations)
    uint32_t A[8][4];
    #pragma unroll
    for (int ks = 0; ks < 8; ks++) {
        A[ks][0] = Ps[mrow * 68 + ks * 8 + q];
        A[ks][1] = Ps[(mrow + 8) * 68 + ks * 8 + q];
        A[ks][2] = Ps[mrow * 68 + ks * 8 + q + 4];
        A[ks][3] = Ps[(mrow + 8) * 68 + ks * 8 + q + 4];
    }
    __syncthreads();   // Ps now reusable as P

    float O[8][4];
    #pragma unroll
    for (int tn = 0; tn < 8; tn++)
        #pragma unroll
        for (int k = 0; k < 4; k++) O[tn][k] = 0.f;
    float m0v = -1e30f, m1v = -1e30f, l0 = 0.f, l1 = 0.f;

    for (int j = 0; j < nj; j++) {
        if (j) { cp_wait<0>(); __syncthreads(); }
        if (j + 1 < nj) load_kv(j + 1, (j + 1) & 1);
        const uint32_t* Ks = sm + 8704 + (j & 1) * ABUF;
        const uint32_t* Vs = sm + 17408 + (j & 1) * ABUF;

        // S = Q @ K^T (already in log2 domain via pre-scaled Q)
        float S[8][4];
        #pragma unroll
        for (int tn = 0; tn < 8; tn++)
            #pragma unroll
            for (int k = 0; k < 4; k++) S[tn][k] = 0.f;
        #pragma unroll
        for (int ks = 0; ks < 8; ks++) {
            #pragma unroll
            for (int tn = 0; tn < 8; tn++) {
                uint32_t b[2];
                b[0] = Ks[(tn * 8 + g) * 68 + ks * 8 + q];
                b[1] = Ks[(tn * 8 + g) * 68 + ks * 8 + q + 4];
                mma8(S[tn], A[ks], b);
            }
        }

        // causal mask (diagonal key-blocks only)
        if (j >= 2 * qb) {
            const int kb = j * 64;
            #pragma unroll
            for (int tn = 0; tn < 8; tn++) {
                const int col = kb + tn * 8 + 2 * q;
                if (col > r0)     S[tn][0] = -1e30f;
                if (col + 1 > r0) S[tn][1] = -1e30f;
                if (col > r1)     S[tn][2] = -1e30f;
                if (col + 1 > r1) S[tn][3] = -1e30f;
            }
        }

        // online softmax (rows r0, r1)
        float tm0 = -1e30f, tm1 = -1e30f;
        #pragma unroll
        for (int tn = 0; tn < 8; tn++) {
            tm0 = fmaxf(tm0, fmaxf(S[tn][0], S[tn][1]));
            tm1 = fmaxf(tm1, fmaxf(S[tn][2], S[tn][3]));
        }
        tm0 = fmaxf(tm0, __shfl_xor_sync(0xffffffffu, tm0, 1));
        tm0 = fmaxf(tm0, __shfl_xor_sync(0xffffffffu, tm0, 2));
        tm1 = fmaxf(tm1, __shfl_xor_sync(0xffffffffu, tm1, 1));
        tm1 = fmaxf(tm1, __shfl_xor_sync(0xffffffffu, tm1, 2));
        const float mn0 = fmaxf(m0v, tm0), mn1 = fmaxf(m1v, tm1);
        const float al0 = ex2(m0v - mn0), al1 = ex2(m1v - mn1);
        m0v = mn0; m1v = mn1;

        float rs0 = 0.f, rs1 = 0.f;
        #pragma unroll
        for (int tn = 0; tn < 8; tn++) {
            S[tn][0] = ex2(S[tn][0] - mn0);
            S[tn][1] = ex2(S[tn][1] - mn0);
            S[tn][2] = ex2(S[tn][2] - mn1);
            S[tn][3] = ex2(S[tn][3] - mn1);
            rs0 += S[tn][0] + S[tn][1];
            rs1 += S[tn][2] + S[tn][3];
        }
        rs0 += __shfl_xor_sync(0xffffffffu, rs0, 1);
        rs0 += __shfl_xor_sync(0xffffffffu, rs0, 2);
        rs1 += __shfl_xor_sync(0xffffffffu, rs1, 1);
        rs1 += __shfl_xor_sync(0xffffffffu, rs1, 2);
        l0 = l0 * al0 + rs0;
        l1 = l1 * al1 + rs1;

        // P -> smem (warp-private rows)
        #pragma unroll
        for (int tn = 0; tn < 8; tn++) {
            uint2 p0 = { tf32r(S[tn][0]), tf32r(S[tn][1]) };
            uint2 p1 = { tf32r(S[tn][2]), tf32r(S[tn][3]) };
            *(uint2*)(Ps + mrow * 68 + tn * 8 + 2 * q) = p0;
            *(uint2*)(Ps + (mrow + 8) * 68 + tn * 8 + 2 * q) = p1;
        }
        __syncwarp();

        // rescale O, accumulate P @ V
        #pragma unroll
        for (int tn = 0; tn < 8; tn++) {
            O[tn][0] *= al0; O[tn][1] *= al0;
            O[tn][2] *= al1; O[tn][3] *= al1;
        }
        #pragma unroll
        for (int ks = 0; ks < 8; ks++) {
            uint32_t a[4];
            a[0] = Ps[mrow * 68 + ks * 8 + q];
            a[1] = Ps[(mrow + 8) * 68 + ks * 8 + q];
            a[2] = Ps[mrow * 68 + ks * 8 + q + 4];
            a[3] = Ps[(mrow + 8) * 68 + ks * 8 + q + 4];
            #pragma unroll
            for (int tn = 0; tn < 8; tn++) {
                uint32_t b[2];
                b[0] = Vs[(tn * 8 + g) * 68 + ks * 8 + q];
                b[1] = Vs[(tn * 8 + g) * 68 + ks * 8 + q + 4];
                mma8(O[tn], a, b);
            }
        }
        __syncwarp();
    }

    // epilogue: normalize, tf32-round for the out-projection GEMM
    const float i0 = 1.f / l0, i1 = 1.f / l1;
    #pragma unroll
    for (int tn = 0; tn < 8; tn++) {
        const int d = tn * 8 + 2 * q;
        uint2 v0 = { tf32r(O[tn][0] * i0), tf32r(O[tn][1] * i0) };
        uint2 v1 = { tf32r(O[tn][2] * i1), tf32r(O[tn][3] * i1) };
        *(uint2*)(g_att + (size_t)r0 * CC + h * DH + d) = v0;
        *(uint2*)(g_att + (size_t)r1 * CC + h * DH + d) = v1;
    }
}

// ---------------- launcher ----------------
extern "C" void kernel_launch(void* const* d_in, const int* in_sizes, int n_in,
                              void* d_out, int out_size)
{
    const float* x  = (const float*)d_in[0];
    const float* wq = (const float*)d_in[1];
    const float* bq = (const float*)d_in[2];
    const float* wk = (const float*)d_in[3];
    const float* bk = (const float*)d_in[4];
    const float* wv = (const float*)d_in[5];
    const float* bv = (const float*)d_in[6];
    const float* wo = (const float*)d_in[7];
    const float* bo = (const float*)d_in[8];

    const int GSM = 2 * GBUFSZ * 4;    // 73728 B
    const int ASM = 26112 * 4;         // 104448 B
    cudaFuncSetAttribute(gemm_k<0>, cudaFuncAttributeMaxDynamicSharedMemorySize, GSM);
    cudaFuncSetAttribute(gemm_k<1>, cudaFuncAttributeMaxDynamicSharedMemorySize, GSM);
    cudaFuncSetAttribute(attn,      cudaFuncAttributeMaxDynamicSharedMemorySize, ASM);

    float* xt_dev;  cudaGetSymbolAddress((void**)&xt_dev,  g_xt);
    float* wt_dev;  cudaGetSymbolAddress((void**)&wt_dev,  g_wt);
    float* wot_dev; cudaGetSymbolAddress((void**)&wot_dev, g_wot);
    float* att_dev; cudaGetSymbolAddress((void**)&att_dev, g_att);

    cvt_x  <<<TT * CC / 1024, 256>>>(x);
    tr_head<<<dim3(12, 12), 256>>>(wq, 0);
    tr_head<<<dim3(12, 12), 256>>>(wk, CC);
    tr_head<<<dim3(12, 12), 256>>>(wv, 2 * CC);
    tr_wo  <<<dim3(12, 12), 256>>>(wo);

    gemm_k<0><<<dim3(32, 18), 256, GSM>>>(xt_dev, wt_dev, bq, bk, bv, nullptr);
    attn<<<dim3(32, 12), 256, ASM>>>();
    gemm_k<1><<<dim3(32, 6), 256, GSM>>>(att_dev, wot_dev, bo, nullptr, nullptr, (float*)d_out);
}

// round 5
// speedup vs baseline: 5.8801x; 1.0953x over previous
#include <cuda_runtime.h>
#include <cstdint>

#define TT 4096
#define CC 768
#define HH 12
#define DH 64

// ---------------- device scratch (allocation-free rule) ----------------
__device__ float g_xt [TT * CC];        // x, tf32-rounded
__device__ float g_q  [HH * TT * DH];   // [h][t][d], pre-scaled by 0.125*log2e, tf32
__device__ float g_k  [HH * TT * DH];   // [h][t][d], tf32
__device__ float g_vt [HH * DH * TT];   // [h][d][t], tf32
__device__ float g_att[TT * CC];        // concat heads, tf32
__device__ float g_wt [3 * CC * CC];    // qkv weights [j][k], tf32
__device__ float g_wot[CC * CC];        // wo as [n][k], tf32

// ---------------- helpers ----------------
static __device__ __forceinline__ uint32_t smem_u32(const void* p) {
    uint32_t a;
    asm("{ .reg .u64 t; cvta.to.shared.u64 t, %1; cvt.u32.u64 %0, t; }" : "=r"(a) : "l"(p));
    return a;
}
static __device__ __forceinline__ uint32_t tf32r(float f) {
    uint32_t u; asm("cvt.rna.tf32.f32 %0, %1;" : "=r"(u) : "f"(f)); return u;
}
static __device__ __forceinline__ float ex2(float x) {
    float y; asm("ex2.approx.f32 %0, %1;" : "=f"(y) : "f"(x)); return y;
}
static __device__ __forceinline__ void mma8(float* d, const uint32_t* a, const uint32_t* b) {
    asm volatile(
        "mma.sync.aligned.m16n8k8.row.col.f32.tf32.tf32.f32 "
        "{%0,%1,%2,%3}, {%4,%5,%6,%7}, {%8,%9}, {%0,%1,%2,%3};"
        : "+f"(d[0]), "+f"(d[1]), "+f"(d[2]), "+f"(d[3])
        : "r"(a[0]), "r"(a[1]), "r"(a[2]), "r"(a[3]), "r"(b[0]), "r"(b[1]));
}
static __device__ __forceinline__ uint4 cvt4(float4 v) {
    uint4 t; t.x = tf32r(v.x); t.y = tf32r(v.y); t.z = tf32r(v.z); t.w = tf32r(v.w);
    return t;
}
static __device__ __forceinline__ void cpa(uint32_t dst, const void* src) {
    asm volatile("cp.async.cg.shared.global [%0], [%1], 16;" :: "r"(dst), "l"(src));
}
static __device__ __forceinline__ void cp_commit() {
    asm volatile("cp.async.commit_group;" ::: "memory");
}
template <int N> static __device__ __forceinline__ void cp_wait() {
    asm volatile("cp.async.wait_group %0;" :: "n"(N) : "memory");
}

// ---------------- producers: tf32 pre-conversion ----------------
__global__ __launch_bounds__(256) void cvt_x(const float* __restrict__ x) {
    int i = blockIdx.x * 256 + threadIdx.x;
    float4 v = ((const float4*)x)[i];
    ((uint4*)g_xt)[i] = cvt4(v);
}
__global__ __launch_bounds__(256) void tr_head(const float* __restrict__ src, int j0) {
    __shared__ float t[64][65];
    const int k0 = blockIdx.x * 64, h = blockIdx.y;
    const float* s = src + (size_t)h * CC * DH;
    #pragma unroll
    for (int i = 0; i < 16; i++) {
        int e = threadIdx.x + i * 256; int kr = e >> 6, d = e & 63;
        t[kr][d] = s[(size_t)(k0 + kr) * DH + d];
    }
    __syncthreads();
    #pragma unroll
    for (int i = 0; i < 16; i++) {
        int e = threadIdx.x + i * 256; int d = e >> 6, kr = e & 63;
        g_wt[(size_t)(j0 + h * DH + d) * CC + k0 + kr] = __uint_as_float(tf32r(t[kr][d]));
    }
}
__global__ __launch_bounds__(256) void tr_wo(const float* __restrict__ wo) {
    __shared__ float t[64][65];
    const int c0 = blockIdx.x * 64, n0 = blockIdx.y * 64;
    #pragma unroll
    for (int i = 0; i < 16; i++) {
        int e = threadIdx.x + i * 256; int cr = e >> 6, n = e & 63;
        t[cr][n] = wo[(size_t)(c0 + cr) * CC + n0 + n];
    }
    __syncthreads();
    #pragma unroll
    for (int i = 0; i < 16; i++) {
        int e = threadIdx.x + i * 256; int n = e >> 6, cr = e & 63;
        g_wot[(size_t)(n0 + n) * CC + c0 + cr] = __uint_as_float(tf32r(t[cr][n]));
    }
}

// ---------------- GEMM (tf32 mma.sync + cp.async): MODE 0 = qkv, MODE 1 = out --------
#define GBUF 4608              // 128*36 u32 per matrix
#define GBUFSZ 9216            // per buffer (A+B)

template <int MODE>
__global__ __launch_bounds__(256, 2) void gemm_k(
    const float* __restrict__ Am, const float* __restrict__ Bm,
    const float* __restrict__ x0, const float* __restrict__ x1,
    const float* __restrict__ x2, float* __restrict__ outp)
{
    extern __shared__ uint32_t sm[];
    const uint32_t usm = smem_u32(sm);
    const int tid = threadIdx.x;
    const int warp = tid >> 5, lane = tid & 31;
    const int g = lane >> 2, q = lane & 3;
    const int warp_m = warp & 3, warp_n = warp >> 2;
    const int m0 = blockIdx.x * 128, n0 = blockIdx.y * 128;

    auto ldgsts = [&](int k0, int buf) {
        const uint32_t uA = usm + buf * GBUFSZ * 4;
        const uint32_t uB = uA + GBUF * 4;
        #pragma unroll
        for (int i = 0; i < 4; i++) {
            int idx = tid + i * 256; int r = idx >> 3, cc = idx & 7;
            cpa(uA + (r * 36 + cc * 4) * 4, Am + (size_t)(m0 + r) * CC + k0 + cc * 4);
            cpa(uB + (r * 36 + cc * 4) * 4, Bm + (size_t)(n0 + r) * CC + k0 + cc * 4);
        }
        cp_commit();
    };

    float Cf[2][8][4];
    #pragma unroll
    for (int tm = 0; tm < 2; tm++)
        #pragma unroll
        for (int tn = 0; tn < 8; tn++)
            #pragma unroll
            for (int k = 0; k < 4; k++) Cf[tm][tn][k] = 0.f;

    ldgsts(0, 0);

    for (int c = 0; c < 24; c++) {
        cp_wait<0>();
        __syncthreads();
        if (c < 23) ldgsts((c + 1) * 32, (c + 1) & 1);
        const uint32_t* sA = sm + (c & 1) * GBUFSZ;
        const uint32_t* sB = sA + GBUF;
        #pragma unroll
        for (int ks = 0; ks < 4; ks++) {
            uint32_t a[2][4];
            #pragma unroll
            for (int tm = 0; tm < 2; tm++) {
                int row = warp_m * 32 + tm * 16 + g;
                a[tm][0] = sA[row * 36 + ks * 8 + q];
                a[tm][1] = sA[(row + 8) * 36 + ks * 8 + q];
                a[tm][2] = sA[row * 36 + ks * 8 + q + 4];
                a[tm][3] = sA[(row + 8) * 36 + ks * 8 + q + 4];
            }
            #pragma unroll
            for (int tn = 0; tn < 8; tn++) {
                uint32_t b[2];
                int col = warp_n * 64 + tn * 8 + g;
                b[0] = sB[col * 36 + ks * 8 + q];
                b[1] = sB[col * 36 + ks * 8 + q + 4];
                mma8(Cf[0][tn], a[0], b);
                mma8(Cf[1][tn], a[1], b);
            }
        }
        __syncthreads();
    }

    const int jb = n0 + warp_n * 64;
    if (MODE == 0) {
        const float c1 = 0.18033688011112042f;   // 0.125 * log2(e)
        const int sel = jb / CC, rem = jb % CC, h = rem >> 6;
        const float* bias = (sel == 0) ? x0 : (sel == 1) ? x1 : x2;
        #pragma unroll
        for (int tm = 0; tm < 2; tm++) {
            const int t0 = m0 + warp_m * 32 + tm * 16 + g;
            #pragma unroll
            for (int tn = 0; tn < 8; tn++) {
                const int d = tn * 8 + 2 * q;
                const float b0 = bias[h * DH + d], b1 = bias[h * DH + d + 1];
                float v00 = Cf[tm][tn][0] + b0, v01 = Cf[tm][tn][1] + b1;
                float v10 = Cf[tm][tn][2] + b0, v11 = Cf[tm][tn][3] + b1;
                if (sel == 0) {
                    float* dst = g_q + (size_t)h * TT * DH;
                    uint2 p0 = { tf32r(v00 * c1), tf32r(v01 * c1) };
                    uint2 p1 = { tf32r(v10 * c1), tf32r(v11 * c1) };
                    *(uint2*)(dst + (size_t)t0 * DH + d) = p0;
                    *(uint2*)(dst + (size_t)(t0 + 8) * DH + d) = p1;
                } else if (sel == 1) {
                    float* dst = g_k + (size_t)h * TT * DH;
                    uint2 p0 = { tf32r(v00), tf32r(v01) };
                    uint2 p1 = { tf32r(v10), tf32r(v11) };
                    *(uint2*)(dst + (size_t)t0 * DH + d) = p0;
                    *(uint2*)(dst + (size_t)(t0 + 8) * DH + d) = p1;
                } else {
                    float* dst = g_vt + (size_t)h * DH * TT;
                    dst[(size_t)d * TT + t0]           = __uint_as_float(tf32r(v00));
                    dst[(size_t)(d + 1) * TT + t0]     = __uint_as_float(tf32r(v01));
                    dst[(size_t)d * TT + t0 + 8]       = __uint_as_float(tf32r(v10));
                    dst[(size_t)(d + 1) * TT + t0 + 8] = __uint_as_float(tf32r(v11));
                }
            }
        }
    } else {
        const float* bo = x0;
        #pragma unroll
        for (int tm = 0; tm < 2; tm++) {
            const int t0 = m0 + warp_m * 32 + tm * 16 + g;
            #pragma unroll
            for (int tn = 0; tn < 8; tn++) {
                const int j = jb + tn * 8 + 2 * q;
                const float b0 = bo[j], b1 = bo[j + 1];
                float2 v0 = { Cf[tm][tn][0] + b0, Cf[tm][tn][1] + b1 };
                float2 v1 = { Cf[tm][tn][2] + b0, Cf[tm][tn][3] + b1 };
                *(float2*)(outp + (size_t)t0 * CC + j) = v0;
                *(float2*)(outp + (size_t)(t0 + 8) * CC + j) = v1;
            }
        }
    }
}

// ---------------- flash attention (tf32 mma.sync, fat-warp tiling) ----------------
// 128 threads = 4 warps; Q block 128 rows; warp = 32 rows (2 m16 tiles) x 64 keys.
// Each K/V b-fragment load feeds 2 mmas (LDS/mma = 1.25 vs 2.25 before).
// smem (u32): Ps[128][68] @0 (Q staging then P), K[2][64][68] @8704, V[2][64][68] @17408.
// Q fragments (64 regs) + O (64) + S (64) in registers; launch_bounds(128,2) -> 256-reg cap.
#define ABUF 4352   // 64*68

__global__ __launch_bounds__(128, 2) void attn()
{
    extern __shared__ uint32_t sm[];
    uint32_t* Ps = sm;
    const uint32_t uPs = smem_u32(sm);

    const int tid = threadIdx.x;
    const int warp = tid >> 5, lane = tid & 31;
    const int g = lane >> 2, q = lane & 3;
    const int qb = 31 - blockIdx.x;    // largest work first
    const int h  = blockIdx.y;
    const int rb = warp * 32;          // warp row base within the 128-row block

    const float* Qg = g_q  + (size_t)h * TT * DH + (size_t)qb * 128 * DH;
    const float* Kg = g_k  + (size_t)h * TT * DH;
    const float* Vg = g_vt + (size_t)h * DH * TT;

    const int nj = 2 * qb + 2;

    auto load_kv = [&](int j, int buf) {
        const uint32_t uK = uPs + (8704 + buf * ABUF) * 4;
        const uint32_t uV = uPs + (17408 + buf * ABUF) * 4;
        #pragma unroll
        for (int i = 0; i < 8; i++) {
            int idx = tid + i * 128; int r = idx >> 4, cc = idx & 15;
            cpa(uK + (r * 68 + cc * 4) * 4, Kg + (size_t)(j * 64 + r) * DH + cc * 4);
            cpa(uV + (r * 68 + cc * 4) * 4, Vg + (size_t)r * TT + j * 64 + cc * 4);
        }
        cp_commit();
    };

    // stage Q into Ps, prefetch KV block 0
    #pragma unroll
    for (int i = 0; i < 16; i++) {
        int idx = tid + i * 128; int r = idx >> 4, cc = idx & 15;
        cpa(uPs + (r * 68 + cc * 4) * 4, Qg + (size_t)r * DH + cc * 4);
    }
    cp_commit();
    load_kv(0, 0);
    cp_wait<0>();
    __syncthreads();

    // Q fragments -> registers: 2 m16 tiles (rows rb+g/rb+8+g and rb+16+g/rb+24+g)
    uint32_t A[2][8][4];
    #pragma unroll
    for (int tm = 0; tm < 2; tm++) {
        const int base = rb + tm * 16;
        #pragma unroll
        for (int ks = 0; ks < 8; ks++) {
            A[tm][ks][0] = Ps[(base + g) * 68 + ks * 8 + q];
            A[tm][ks][1] = Ps[(base + 8 + g) * 68 + ks * 8 + q];
            A[tm][ks][2] = Ps[(base + g) * 68 + ks * 8 + q + 4];
            A[tm][ks][3] = Ps[(base + 8 + g) * 68 + ks * 8 + q + 4];
        }
    }
    __syncthreads();   // Ps now reusable as P (rows are warp-private anyway)

    float O[2][8][4];
    #pragma unroll
    for (int tm = 0; tm < 2; tm++)
        #pragma unroll
        for (int tn = 0; tn < 8; tn++)
            #pragma unroll
            for (int k = 0; k < 4; k++) O[tm][tn][k] = 0.f;
    float mv[4], lv[4];
    #pragma unroll
    for (int i = 0; i < 4; i++) { mv[i] = -1e30f; lv[i] = 0.f; }

    // global rows handled by this thread: r0=rb+g, r1=+8, r2=+16, r3=+24
    const int r0 = qb * 128 + rb + g;

    for (int j = 0; j < nj; j++) {
        if (j) { cp_wait<0>(); __syncthreads(); }
        if (j + 1 < nj) load_kv(j + 1, (j + 1) & 1);
        const uint32_t* Ks = sm + 8704 + (j & 1) * ABUF;
        const uint32_t* Vs = sm + 17408 + (j & 1) * ABUF;

        // S = Q @ K^T (log2 domain; Q pre-scaled)
        float S[2][8][4];
        #pragma unroll
        for (int tm = 0; tm < 2; tm++)
            #pragma unroll
            for (int tn = 0; tn < 8; tn++)
                #pragma unroll
                for (int k = 0; k < 4; k++) S[tm][tn][k] = 0.f;
        #pragma unroll
        for (int ks = 0; ks < 8; ks++) {
            #pragma unroll
            for (int tn = 0; tn < 8; tn++) {
                uint32_t b[2];
                b[0] = Ks[(tn * 8 + g) * 68 + ks * 8 + q];
                b[1] = Ks[(tn * 8 + g) * 68 + ks * 8 + q + 4];
                mma8(S[0][tn], A[0][ks], b);
                mma8(S[1][tn], A[1][ks], b);
            }
        }

        // causal mask (diagonal key-blocks only)
        if (j >= 2 * qb) {
            const int kb = j * 64;
            #pragma unroll
            for (int tn = 0; tn < 8; tn++) {
                const int col = kb + tn * 8 + 2 * q;
                #pragma unroll
                for (int tm = 0; tm < 2; tm++) {
                    const int ra = r0 + tm * 16, rb2 = ra + 8;
                    if (col > ra)      S[tm][tn][0] = -1e30f;
                    if (col + 1 > ra)  S[tm][tn][1] = -1e30f;
                    if (col > rb2)     S[tm][tn][2] = -1e30f;
                    if (col + 1 > rb2) S[tm][tn][3] = -1e30f;
                }
            }
        }

        // online softmax over 4 rows
        float tmax[4] = { -1e30f, -1e30f, -1e30f, -1e30f };
        #pragma unroll
        for (int tm = 0; tm < 2; tm++)
            #pragma unroll
            for (int tn = 0; tn < 8; tn++) {
                tmax[tm * 2]     = fmaxf(tmax[tm * 2],     fmaxf(S[tm][tn][0], S[tm][tn][1]));
                tmax[tm * 2 + 1] = fmaxf(tmax[tm * 2 + 1], fmaxf(S[tm][tn][2], S[tm][tn][3]));
            }
        float al[4];
        #pragma unroll
        for (int i = 0; i < 4; i++) {
            tmax[i] = fmaxf(tmax[i], __shfl_xor_sync(0xffffffffu, tmax[i], 1));
            tmax[i] = fmaxf(tmax[i], __shfl_xor_sync(0xffffffffu, tmax[i], 2));
            const float mn = fmaxf(mv[i], tmax[i]);
            al[i] = ex2(mv[i] - mn);
            mv[i] = mn;
        }
        float rs[4] = { 0.f, 0.f, 0.f, 0.f };
        #pragma unroll
        for (int tm = 0; tm < 2; tm++)
            #pragma unroll
            for (int tn = 0; tn < 8; tn++) {
                S[tm][tn][0] = ex2(S[tm][tn][0] - mv[tm * 2]);
                S[tm][tn][1] = ex2(S[tm][tn][1] - mv[tm * 2]);
                S[tm][tn][2] = ex2(S[tm][tn][2] - mv[tm * 2 + 1]);
                S[tm][tn][3] = ex2(S[tm][tn][3] - mv[tm * 2 + 1]);
                rs[tm * 2]     += S[tm][tn][0] + S[tm][tn][1];
                rs[tm * 2 + 1] += S[tm][tn][2] + S[tm][tn][3];
            }
        #pragma unroll
        for (int i = 0; i < 4; i++) {
            rs[i] += __shfl_xor_sync(0xffffffffu, rs[i], 1);
            rs[i] += __shfl_xor_sync(0xffffffffu, rs[i], 2);
            lv[i] = lv[i] * al[i] + rs[i];
        }

        // P -> smem (warp-private rows)
        #pragma unroll
        for (int tm = 0; tm < 2; tm++) {
            const int base = rb + tm * 16;
            #pragma unroll
            for (int tn = 0; tn < 8; tn++) {
                uint2 p0 = { tf32r(S[tm][tn][0]), tf32r(S[tm][tn][1]) };
                uint2 p1 = { tf32r(S[tm][tn][2]), tf32r(S[tm][tn][3]) };
                *(uint2*)(Ps + (base + g) * 68 + tn * 8 + 2 * q) = p0;
                *(uint2*)(Ps + (base + 8 + g) * 68 + tn * 8 + 2 * q) = p1;
            }
        }
        __syncwarp();

        // rescale O, accumulate P @ V
        #pragma unroll
        for (int tm = 0; tm < 2; tm++)
            #pragma unroll
            for (int tn = 0; tn < 8; tn++) {
                O[tm][tn][0] *= al[tm * 2];     O[tm][tn][1] *= al[tm * 2];
                O[tm][tn][2] *= al[tm * 2 + 1]; O[tm][tn][3] *= al[tm * 2 + 1];
            }
        #pragma unroll
        for (int ks = 0; ks < 8; ks++) {
            uint32_t a[2][4];
            #pragma unroll
            for (int tm = 0; tm < 2; tm++) {
                const int base = rb + tm * 16;
                a[tm][0] = Ps[(base + g) * 68 + ks * 8 + q];
                a[tm][1] = Ps[(base + 8 + g) * 68 + ks * 8 + q];
                a[tm][2] = Ps[(base + g) * 68 + ks * 8 + q + 4];
                a[tm][3] = Ps[(base + 8 + g) * 68 + ks * 8 + q + 4];
            }
            #pragma unroll
            for (int tn = 0; tn < 8; tn++) {
                uint32_t b[2];
                b[0] = Vs[(tn * 8 + g) * 68 + ks * 8 + q];
                b[1] = Vs[(tn * 8 + g) * 68 + ks * 8 + q + 4];
                mma8(O[0][tn], a[0], b);
                mma8(O[1][tn], a[1], b);
            }
        }
        __syncwarp();
    }

    // epilogue: normalize, tf32-round for the out-projection GEMM
    #pragma unroll
    for (int tm = 0; tm < 2; tm++) {
        const int ra = r0 + tm * 16;
        const float i0 = 1.f / lv[tm * 2], i1 = 1.f / lv[tm * 2 + 1];
        #pragma unroll
        for (int tn = 0; tn < 8; tn++) {
            const int d = tn * 8 + 2 * q;
            uint2 v0 = { tf32r(O[tm][tn][0] * i0), tf32r(O[tm][tn][1] * i0) };
            uint2 v1 = { tf32r(O[tm][tn][2] * i1), tf32r(O[tm][tn][3] * i1) };
            *(uint2*)(g_att + (size_t)ra * CC + h * DH + d) = v0;
            *(uint2*)(g_att + (size_t)(ra + 8) * CC + h * DH + d) = v1;
        }
    }
}

// ---------------- launcher ----------------
extern "C" void kernel_launch(void* const* d_in, const int* in_sizes, int n_in,
                              void* d_out, int out_size)
{
    const float* x  = (const float*)d_in[0];
    const float* wq = (const float*)d_in[1];
    const float* bq = (const float*)d_in[2];
    const float* wk = (const float*)d_in[3];
    const float* bk = (const float*)d_in[4];
    const float* wv = (const float*)d_in[5];
    const float* bv = (const float*)d_in[6];
    const float* wo = (const float*)d_in[7];
    const float* bo = (const float*)d_in[8];

    const int GSM = 2 * GBUFSZ * 4;    // 73728 B
    const int ASM = 26112 * 4;         // 104448 B
    cudaFuncSetAttribute(gemm_k<0>, cudaFuncAttributeMaxDynamicSharedMemorySize, GSM);
    cudaFuncSetAttribute(gemm_k<1>, cudaFuncAttributeMaxDynamicSharedMemorySize, GSM);
    cudaFuncSetAttribute(attn,      cudaFuncAttributeMaxDynamicSharedMemorySize, ASM);

    float* xt_dev;  cudaGetSymbolAddress((void**)&xt_dev,  g_xt);
    float* wt_dev;  cudaGetSymbolAddress((void**)&wt_dev,  g_wt);
    float* wot_dev; cudaGetSymbolAddress((void**)&wot_dev, g_wot);
    float* att_dev; cudaGetSymbolAddress((void**)&att_dev, g_att);

    cvt_x  <<<TT * CC / 1024, 256>>>(x);
    tr_head<<<dim3(12, 12), 256>>>(wq, 0);
    tr_head<<<dim3(12, 12), 256>>>(wk, CC);
    tr_head<<<dim3(12, 12), 256>>>(wv, 2 * CC);
    tr_wo  <<<dim3(12, 12), 256>>>(wo);

    gemm_k<0><<<dim3(32, 18), 256, GSM>>>(xt_dev, wt_dev, bq, bk, bv, nullptr);
    attn<<<dim3(32, 12), 128, ASM>>>();
    gemm_k<1><<<dim3(32, 6), 256, GSM>>>(att_dev, wot_dev, bo, nullptr, nullptr, (float*)d_out);
}